// round 8
// baseline (speedup 1.0000x reference)
#include <cuda_runtime.h>
#include <math.h>

#define NN 140
#define TT 12
#define BB 32
#define HH 128
#define HID 140
#define G3 420   // 3*HID
#define BT 384   // BB*TT

typedef unsigned long long u64;

__device__ __forceinline__ u64 pack2(float s) {
    u64 d;
    asm("mov.b64 %0, {%1, %1};" : "=l"(d) : "f"(s));
    return d;
}
__device__ __forceinline__ void fma2(u64& d, u64 a, u64 b) {
    asm("fma.rn.f32x2 %0, %1, %2, %0;" : "+l"(d) : "l"(a), "l"(b));
}
__device__ __forceinline__ u64 add2(u64 a, u64 b) {
    u64 d;
    asm("add.rn.f32x2 %0, %1, %2;" : "=l"(d) : "l"(a), "l"(b));
    return d;
}

// ---------------- scratch (device globals; no runtime alloc) ----------------
__device__ float g_xsupT[(size_t)NN * HH * BT];       // [n][h][bt]
__device__ float g_gi[(size_t)NN * BT * G3];          // [n][bt][g]
__device__ float g_outs[(size_t)NN * BB * TT * HID];  // [n][b][t][j]
__device__ float g_ln[(size_t)BB * NN * HID];         // [b][n][j]
__device__ float g_q[(size_t)BB * NN * HID];
__device__ float g_k[(size_t)BB * NN * HID];
__device__ float g_att[NN * NN];
__device__ float g_anorm[NN * NN];
__device__ float g_whhT[(size_t)NN * HID * G3];       // [n][jj][g]
__device__ float g_wihT[(size_t)NN * HH * G3];        // [n][k][g]
// packed transposed weights: w4[k4*140 + jp] = {w[jp][4k4..4k4+3]}
__device__ float4 g_wr4[35 * HID];   // attn_w right half (gru_outs part)
__device__ float4 g_wl4[35 * HID];   // attn_w left half (hid part)
__device__ float4 g_wq4[35 * HID];
__device__ float4 g_wk4[35 * HID];

// ---------------- Kernel P: transpose whh -> whhT (tiled) --------------------
__global__ void kP(const float* __restrict__ whh) {
    __shared__ float tile[32][33];
    int n = blockIdx.x, gt = blockIdx.y * 32, jt = blockIdx.z * 32;
    int tx = threadIdx.x, ty = threadIdx.y;
    const float* src = whh + (size_t)n * G3 * HID;
    float* dst = g_whhT + (size_t)n * HID * G3;
    int g = gt + ty, jj = jt + tx;
    tile[ty][tx] = (g < G3 && jj < HID) ? src[(size_t)g * HID + jj] : 0.f;
    __syncthreads();
    int jj2 = jt + ty, g2 = gt + tx;
    if (jj2 < HID && g2 < G3) dst[(size_t)jj2 * G3 + g2] = tile[tx][ty];
}

// ---------------- Kernel P2: transpose wih -> wihT (tiled) -------------------
__global__ void kP2(const float* __restrict__ wih) {
    __shared__ float tile[32][33];
    int n = blockIdx.x, gt = blockIdx.y * 32, jt = blockIdx.z * 32;
    int tx = threadIdx.x, ty = threadIdx.y;
    const float* src = wih + (size_t)n * G3 * HH;
    float* dst = g_wihT + (size_t)n * HH * G3;
    int g = gt + ty, jj = jt + tx;
    tile[ty][tx] = (g < G3 && jj < HH) ? src[(size_t)g * HH + jj] : 0.f;
    __syncthreads();
    int jj2 = jt + ty, g2 = gt + tx;
    if (jj2 < HH && g2 < G3) dst[(size_t)jj2 * G3 + g2] = tile[tx][ty];
}

// ---------------- Kernel T: pack weights k4-major + zero g_att ---------------
__global__ void kT(const float* __restrict__ attn_w, const float* __restrict__ wq,
                   const float* __restrict__ wk) {
    int idx = blockIdx.x * 256 + threadIdx.x;  // 0..19599 (= 4*4900)
    if (idx >= 4 * 4900) return;
    g_att[idx] = 0.f;
    int mat = idx / 4900, r = idx - mat * 4900;
    int k4 = r / HID, jp = r - k4 * HID;
    const float* src;
    if (mat == 0)      src = attn_w + jp * 280 + HID + 4 * k4;
    else if (mat == 1) src = attn_w + jp * 280 + 4 * k4;
    else if (mat == 2) src = wq + jp * HID + 4 * k4;
    else               src = wk + jp * HID + 4 * k4;
    float4 v = make_float4(src[0], src[1], src[2], src[3]);
    float4* dst = (mat == 0) ? g_wr4 : (mat == 1) ? g_wl4 : (mat == 2) ? g_wq4 : g_wk4;
    dst[k4 * HID + jp] = v;
}

// ---------------- Kernel A: fused seq1 MLP -> x_sup^T (K-major) --------------
__global__ void kA(const float* __restrict__ x, const float* __restrict__ w1,
                   const float* __restrict__ b1, const float* __restrict__ w2,
                   const float* __restrict__ b2) {
    int n = blockIdx.x;
    int bt = threadIdx.x;  // 384 threads
    __shared__ float w1s[64], b1s[64], b2s[128];
    __shared__ float w2s[128 * 64];
    for (int i = threadIdx.x; i < 64; i += 384) { w1s[i] = w1[i]; b1s[i] = b1[i]; }
    for (int i = threadIdx.x; i < 128; i += 384) b2s[i] = b2[i];
    for (int i = threadIdx.x; i < 128 * 64; i += 384) w2s[i] = w2[i];
    __syncthreads();
    float s = x[bt * NN + n];
    float h1[64];
#pragma unroll
    for (int e = 0; e < 64; e++) h1[e] = fmaxf(fmaf(s, w1s[e], b1s[e]), 0.f);
    float* dst = g_xsupT + (size_t)n * HH * BT + bt;
    for (int h = 0; h < 128; h++) {
        float acc = b2s[h];
        const float4* wr = (const float4*)&w2s[h * 64];
#pragma unroll
        for (int e4 = 0; e4 < 16; e4++) {
            float4 w = wr[e4];
            acc += w.x * h1[e4 * 4] + w.y * h1[e4 * 4 + 1] + w.z * h1[e4 * 4 + 2] + w.w * h1[e4 * 4 + 3];
        }
        dst[(size_t)h * BT] = fmaxf(acc, 0.f);
    }
}

// ---------------- Kernel B v3: gi = x_sup @ wihT + bih (f32x2) ---------------
#define XSTR 132
__global__ void kB(const float* __restrict__ bih) {
    __shared__ float xs_s[32 * XSTR];
    int n = blockIdx.x, bt0 = blockIdx.y * 32;
    int tid = threadIdx.x;  // 512
    for (int idx = tid; idx < 32 * HH; idx += 512) {
        int k = idx >> 5, bt = idx & 31;
        xs_s[bt * XSTR + k] = g_xsupT[((size_t)n * HH + k) * BT + bt0 + bt];
    }
    __syncthreads();
    int g4 = tid & 127, bgrp = tid >> 7;
    if (g4 >= 105) return;
    const float* wT = g_wihT + (size_t)n * HH * G3;
    u64 a01[8], a23[8];
#pragma unroll
    for (int i = 0; i < 8; i++) { a01[i] = 0ull; a23[i] = 0ull; }
#pragma unroll 4
    for (int k4 = 0; k4 < 32; k4++) {
        ulonglong2 w0 = __ldg((const ulonglong2*)&wT[(size_t)(4 * k4 + 0) * G3 + 4 * g4]);
        ulonglong2 w1 = __ldg((const ulonglong2*)&wT[(size_t)(4 * k4 + 1) * G3 + 4 * g4]);
        ulonglong2 w2 = __ldg((const ulonglong2*)&wT[(size_t)(4 * k4 + 2) * G3 + 4 * g4]);
        ulonglong2 w3 = __ldg((const ulonglong2*)&wT[(size_t)(4 * k4 + 3) * G3 + 4 * g4]);
#pragma unroll
        for (int i = 0; i < 8; i++) {
            float4 xv = *(const float4*)&xs_s[(bgrp * 8 + i) * XSTR + 4 * k4];
            u64 px = pack2(xv.x), py = pack2(xv.y), pz = pack2(xv.z), pw = pack2(xv.w);
            fma2(a01[i], px, w0.x); fma2(a23[i], px, w0.y);
            fma2(a01[i], py, w1.x); fma2(a23[i], py, w1.y);
            fma2(a01[i], pz, w2.x); fma2(a23[i], pz, w2.y);
            fma2(a01[i], pw, w3.x); fma2(a23[i], pw, w3.y);
        }
    }
    ulonglong2 bb = *(const ulonglong2*)&bih[n * G3 + 4 * g4];
#pragma unroll
    for (int i = 0; i < 8; i++) {
        int bt = bt0 + bgrp * 8 + i;
        ulonglong2 o;
        o.x = add2(a01[i], bb.x);
        o.y = add2(a23[i], bb.y);
        *(ulonglong2*)&g_gi[((size_t)n * BT + bt) * G3 + 4 * g4] = o;
    }
}

// ---------------- Kernel C v4: GRU scan (f32x2, coalesced whhT) --------------
#define HSTR 144
#define GHSTR 424
__global__ void kC(const float* __restrict__ bhh) {
    extern __shared__ float sm[];
    float* h_s = sm;                 // 32*144
    float* gh_s = sm + 32 * HSTR;    // 32*424
    int n = blockIdx.x, tid = threadIdx.x;  // 512 thr
    for (int i = tid; i < 32 * HSTR; i += 512) h_s[i] = 0.f;
    int bgrp = tid >> 7;          // 0..3  (8 batches each)
    int g4 = tid & 127;           // float4 group of g; active if < 105
    bool act = g4 < 105;
    const float* whhT_n = g_whhT + (size_t)n * HID * G3;
    const float* bhh_n = bhh + n * G3;
    const float* gi_n = g_gi + (size_t)n * BT * G3;
    float* outs_n = g_outs + (size_t)n * BB * TT * HID;
    u64 b01 = 0ull, b23 = 0ull;
    if (act) {
        ulonglong2 bb = *(const ulonglong2*)&bhh_n[4 * g4];
        b01 = bb.x; b23 = bb.y;
    }
    for (int t = 0; t < TT; t++) {
        __syncthreads();
        if (act) {
            u64 a01[8], a23[8];
#pragma unroll
            for (int i = 0; i < 8; i++) { a01[i] = 0ull; a23[i] = 0ull; }
#pragma unroll 5
            for (int jj4 = 0; jj4 < 35; jj4++) {
                ulonglong2 w0 = __ldg((const ulonglong2*)&whhT_n[(size_t)(jj4 * 4 + 0) * G3 + 4 * g4]);
                ulonglong2 w1 = __ldg((const ulonglong2*)&whhT_n[(size_t)(jj4 * 4 + 1) * G3 + 4 * g4]);
                ulonglong2 w2 = __ldg((const ulonglong2*)&whhT_n[(size_t)(jj4 * 4 + 2) * G3 + 4 * g4]);
                ulonglong2 w3 = __ldg((const ulonglong2*)&whhT_n[(size_t)(jj4 * 4 + 3) * G3 + 4 * g4]);
#pragma unroll
                for (int i = 0; i < 8; i++) {
                    float4 hv = *(const float4*)&h_s[(bgrp * 8 + i) * HSTR + jj4 * 4];
                    u64 px = pack2(hv.x), py = pack2(hv.y), pz = pack2(hv.z), pw = pack2(hv.w);
                    fma2(a01[i], px, w0.x); fma2(a23[i], px, w0.y);
                    fma2(a01[i], py, w1.x); fma2(a23[i], py, w1.y);
                    fma2(a01[i], pz, w2.x); fma2(a23[i], pz, w2.y);
                    fma2(a01[i], pw, w3.x); fma2(a23[i], pw, w3.y);
                }
            }
#pragma unroll
            for (int i = 0; i < 8; i++) {
                ulonglong2 o;
                o.x = add2(a01[i], b01);
                o.y = add2(a23[i], b23);
                *(ulonglong2*)&gh_s[(bgrp * 8 + i) * GHSTR + 4 * g4] = o;
            }
        }
        __syncthreads();
        for (int idx = tid; idx < BB * HID; idx += 512) {
            int b = idx / HID, j = idx - b * HID;
            const float* gi = gi_n + (size_t)(b * TT + t) * G3;
            float gir = gi[j], giz = gi[HID + j], gin = gi[2 * HID + j];
            float ghr = gh_s[b * GHSTR + j];
            float ghz = gh_s[b * GHSTR + HID + j];
            float ghn = gh_s[b * GHSTR + 2 * HID + j];
            float r = 1.f / (1.f + expf(-(gir + ghr)));
            float z = 1.f / (1.f + expf(-(giz + ghz)));
            float nv = tanhf(gin + r * ghn);
            float hold = h_s[b * HSTR + j];
            float hnew = (1.f - z) * nv + z * hold;
            h_s[b * HSTR + j] = hnew;
            outs_n[(size_t)(b * TT + t) * HID + j] = hnew;
        }
    }
}

// ---------------- Kernel D: temporal attention + LayerNorm (jp-per-thread) ---
__global__ void kD(const float* __restrict__ attn_b, const float* __restrict__ attn_v,
                   const float* __restrict__ ln_g, const float* __restrict__ ln_b) {
    __shared__ float outs_s[TT * HID];   // 1680
    __shared__ float wpart[5][12];
    __shared__ float ws[12];
    __shared__ float red[5][2];
    __shared__ float stats[2];
    int bid = blockIdx.x;
    int n = bid >> 5, b = bid & 31;
    int tid = threadIdx.x;  // 160
    const float* src = g_outs + (size_t)(n * BB + b) * TT * HID;
    for (int i = tid; i < TT * HID; i += 160) outs_s[i] = src[i];
    __syncthreads();
    int jp = tid;
    bool act = jp < HID;
    float acc[13];
#pragma unroll
    for (int t = 0; t < 13; t++) acc[t] = 0.f;
    if (act) {
#pragma unroll 5
        for (int k4 = 0; k4 < 35; k4++) {
            float4 wr = g_wr4[k4 * HID + jp];
            float4 wl = g_wl4[k4 * HID + jp];
#pragma unroll
            for (int t = 0; t < 12; t++) {
                float4 s = *(const float4*)&outs_s[t * HID + 4 * k4];
                acc[t] += s.x * wr.x + s.y * wr.y + s.z * wr.z + s.w * wr.w;
                if (t == 11) acc[12] += s.x * wl.x + s.y * wl.y + s.z * wl.z + s.w * wl.w;
            }
        }
    }
    float eh = act ? (acc[12] + attn_b[jp]) : 0.f;
    float vv = act ? attn_v[jp] : 0.f;
    float p[12];
#pragma unroll
    for (int t = 0; t < 12; t++) p[t] = vv * tanhf(eh + acc[t]);
#pragma unroll
    for (int o = 16; o; o >>= 1)
#pragma unroll
        for (int t = 0; t < 12; t++) p[t] += __shfl_xor_sync(0xffffffff, p[t], o);
    int wid = tid >> 5, lane = tid & 31;
    if (lane == 0)
#pragma unroll
        for (int t = 0; t < 12; t++) wpart[wid][t] = p[t];
    __syncthreads();
    if (tid == 0) {
        float scv[12], m = -3.4e38f;
#pragma unroll
        for (int t = 0; t < 12; t++) {
            float v = wpart[0][t] + wpart[1][t] + wpart[2][t] + wpart[3][t] + wpart[4][t];
            scv[t] = v;
            m = fmaxf(m, v);
        }
        float ssum = 0.f;
#pragma unroll
        for (int t = 0; t < 12; t++) { float e = expf(scv[t] - m); ws[t] = e; ssum += e; }
        float inv = 1.f / ssum;
#pragma unroll
        for (int t = 0; t < 12; t++) ws[t] *= inv;
    }
    __syncthreads();
    float pre = 0.f;
    if (act) {
        pre = outs_s[11 * HID + jp];  // + hid
#pragma unroll
        for (int t = 0; t < 12; t++) pre += ws[t] * outs_s[t * HID + jp];
    }
    float s = act ? pre : 0.f, q = act ? pre * pre : 0.f;
#pragma unroll
    for (int o = 16; o; o >>= 1) {
        s += __shfl_xor_sync(0xffffffff, s, o);
        q += __shfl_xor_sync(0xffffffff, q, o);
    }
    if (lane == 0) { red[wid][0] = s; red[wid][1] = q; }
    __syncthreads();
    if (tid == 0) {
        float ss = red[0][0] + red[1][0] + red[2][0] + red[3][0] + red[4][0];
        float qq = red[0][1] + red[1][1] + red[2][1] + red[3][1] + red[4][1];
        float mu = ss * (1.f / HID);
        stats[0] = mu;
        stats[1] = qq * (1.f / HID) - mu * mu;
    }
    __syncthreads();
    if (act) {
        float mu = stats[0], inv = rsqrtf(stats[1] + 1e-5f);
        g_ln[((size_t)b * NN + n) * HID + jp] = (pre - mu) * inv * ln_g[jp] + ln_b[jp];
    }
}

// ---------------- Kernel E1: q,k projections (jp-per-thread, packed W) -------
__global__ void kE1(const float* __restrict__ bq, const float* __restrict__ bk) {
    __shared__ float src_s[28 * HID];
    int b = blockIdx.x, mat = blockIdx.y, chunk = blockIdx.z;
    int tid = threadIdx.x;  // 160
    int i0 = chunk * 28;
    const float* src = g_ln + (size_t)b * NN * HID + (size_t)i0 * HID;
    for (int i = tid; i < 28 * HID; i += 160) src_s[i] = src[i];
    __syncthreads();
    int jp = tid;
    if (jp >= HID) return;
    const float4* wmat = mat ? g_wk4 : g_wq4;
    float acc[28];
#pragma unroll
    for (int ii = 0; ii < 28; ii++) acc[ii] = 0.f;
#pragma unroll 5
    for (int k4 = 0; k4 < 35; k4++) {
        float4 w = wmat[k4 * HID + jp];
#pragma unroll
        for (int ii = 0; ii < 28; ii++) {
            float4 sv = *(const float4*)&src_s[ii * HID + 4 * k4];
            acc[ii] += sv.x * w.x + sv.y * w.y + sv.z * w.z + sv.w * w.w;
        }
    }
    float bias = (mat ? bk : bq)[jp];
    float* dst = (mat ? g_k : g_q) + (size_t)b * NN * HID;
#pragma unroll
    for (int ii = 0; ii < 28; ii++) dst[(size_t)(i0 + ii) * HID + jp] = acc[ii] + bias;
}

// ---------------- Kernel E2: per (b,head) softmax, accumulate mean -----------
__global__ void kE2() {
    __shared__ float qs[NN * 28], ks[NN * 28];
    int bid = blockIdx.x;
    int b = bid / 5, h = bid - b * 5;
    int tid = threadIdx.x;  // 128
    const float* qsrc = g_q + (size_t)b * NN * HID + h * 28;
    const float* ksrc = g_k + (size_t)b * NN * HID + h * 28;
    for (int idx = tid; idx < NN * 28; idx += 128) {
        int i = idx / 28, d = idx - i * 28;
        qs[idx] = qsrc[i * HID + d];
        ks[idx] = ksrc[i * HID + d];
    }
    __syncthreads();
    const float scale = 0.1889822365046136f;  // 1/sqrt(28)
    int wid = tid >> 5, lane = tid & 31;
    for (int i = wid; i < NN; i += 4) {
        float lg[5];
#pragma unroll
        for (int u = 0; u < 5; u++) {
            int k = lane + 32 * u;
            float acc = -3.4e38f;
            if (k < NN) {
                acc = 0.f;
                const float4* a4 = (const float4*)&qs[i * 28];
                const float4* b4 = (const float4*)&ks[k * 28];
#pragma unroll
                for (int q = 0; q < 7; q++) {
                    float4 a = a4[q], c = b4[q];
                    acc += a.x * c.x + a.y * c.y + a.z * c.z + a.w * c.w;
                }
                acc *= scale;
            }
            lg[u] = acc;
        }
        float m = lg[0];
#pragma unroll
        for (int u = 1; u < 5; u++) m = fmaxf(m, lg[u]);
        for (int o = 16; o; o >>= 1) m = fmaxf(m, __shfl_xor_sync(0xffffffff, m, o));
        float s = 0.f, e[5];
#pragma unroll
        for (int u = 0; u < 5; u++) {
            int k = lane + 32 * u;
            e[u] = (k < NN) ? expf(lg[u] - m) : 0.f;
            s += e[u];
        }
        for (int o = 16; o; o >>= 1) s += __shfl_xor_sync(0xffffffff, s, o);
        float inv = 1.f / (160.f * s);
#pragma unroll
        for (int u = 0; u < 5; u++) {
            int k = lane + 32 * u;
            if (k < NN) atomicAdd(&g_att[i * NN + k], e[u] * inv);
        }
    }
}

// ---------------- Kernel F: A_norm + write attention output ------------------
__global__ void kF(float* __restrict__ d_out) {
    __shared__ float dinv[NN];
    int tid = threadIdx.x;  // 256
    for (int i = tid; i < NN; i += 256) {
        float s = 1.f;
        for (int j = 0; j < NN; j++) s += g_att[i * NN + j];
        dinv[i] = 1.f / sqrtf(s);
    }
    __syncthreads();
    for (int idx = tid; idx < NN * NN; idx += 256) {
        int i = idx / NN, j = idx - i * NN;
        float a = g_att[idx] + (i == j ? 1.f : 0.f);
        g_anorm[idx] = dinv[i] * a * dinv[j];
        d_out[BB * 3 * NN + idx] = g_att[idx];
    }
}

// ---------------- Kernel G: fcta + GCN x2 + FC head + output -----------------
__global__ void kG(const float* __restrict__ fcta_w, const float* __restrict__ fcta_b,
                   const float* __restrict__ gcn1_w, const float* __restrict__ gcn1_b,
                   const float* __restrict__ gcn2_w, const float* __restrict__ gcn2_b,
                   const float* __restrict__ fc_w1, const float* __restrict__ fc_b1,
                   const float* __restrict__ fc_w2, const float* __restrict__ fc_b2,
                   float* __restrict__ d_out) {
    __shared__ float wrs[NN * TT];   // reused as f1
    __shared__ float Y[NN * 32];
    __shared__ float X[NN * 32];
    int b = blockIdx.x;
    int tid = threadIdx.x;  // 256
    const float* ln = g_ln + (size_t)b * NN * HID;
    for (int idx = tid; idx < NN * TT; idx += 256) {
        int i = idx / TT, t = idx - i * TT;
        const float4* s4 = (const float4*)(ln + i * HID);
        const float4* w4 = (const float4*)(fcta_w + t * HID);
        float acc = fcta_b[t];
#pragma unroll 7
        for (int q = 0; q < 35; q++) {
            float4 a = s4[q], c = w4[q];
            acc += a.x * c.x + a.y * c.y + a.z * c.z + a.w * c.w;
        }
        wrs[idx] = acc;
    }
    __syncthreads();
    for (int idx = tid; idx < NN * 32; idx += 256) {
        int i = idx >> 5, c = idx & 31;
        float acc = 0.f;
#pragma unroll
        for (int t = 0; t < TT; t++) acc += wrs[i * TT + t] * gcn1_w[t * 32 + c];
        Y[idx] = acc;
    }
    __syncthreads();
    for (int idx = tid; idx < NN * 32; idx += 256) {
        int i = idx >> 5, c = idx & 31;
        float acc = gcn1_b[c];
        const float* ar = g_anorm + i * NN;
        for (int j = 0; j < NN; j++) acc += __ldg(&ar[j]) * Y[j * 32 + c];
        X[idx] = fmaxf(acc, 0.f);
    }
    __syncthreads();
    for (int idx = tid; idx < NN * 32; idx += 256) {
        int i = idx >> 5, c = idx & 31;
        float acc = 0.f;
#pragma unroll
        for (int cc = 0; cc < 32; cc++) acc += X[i * 32 + cc] * gcn2_w[cc * 32 + c];
        Y[idx] = acc;
    }
    __syncthreads();
    for (int idx = tid; idx < NN * 32; idx += 256) {
        int i = idx >> 5, c = idx & 31;
        float acc = gcn2_b[c];
        const float* ar = g_anorm + i * NN;
        for (int j = 0; j < NN; j++) acc += __ldg(&ar[j]) * Y[j * 32 + c];
        X[idx] = fmaxf(acc, 0.f);
    }
    __syncthreads();
    for (int idx = tid; idx < NN * TT; idx += 256) {
        int i = idx / TT, t = idx - i * TT;
        float acc = fc_b1[t];
#pragma unroll
        for (int c = 0; c < 32; c++) acc += X[i * 32 + c] * fc_w1[t * 32 + c];
        wrs[idx] = (acc > 0.f) ? acc : 0.01f * acc;
    }
    __syncthreads();
    for (int idx = tid; idx < NN * 3; idx += 256) {
        int hz = idx / NN, i = idx - hz * NN;
        float acc = fc_b2[hz];
#pragma unroll
        for (int t = 0; t < TT; t++) acc += wrs[i * TT + t] * fc_w2[hz * TT + t];
        d_out[(b * 3 + hz) * NN + i] = acc;
    }
}

// ---------------- launch ------------------------------------------------------
extern "C" void kernel_launch(void* const* d_in, const int* in_sizes, int n_in,
                              void* d_out, int out_size) {
    const float* x       = (const float*)d_in[0];
    const float* seq1_w1 = (const float*)d_in[1];
    const float* seq1_b1 = (const float*)d_in[2];
    const float* seq1_w2 = (const float*)d_in[3];
    const float* seq1_b2 = (const float*)d_in[4];
    const float* gru_wih = (const float*)d_in[5];
    const float* gru_whh = (const float*)d_in[6];
    const float* gru_bih = (const float*)d_in[7];
    const float* gru_bhh = (const float*)d_in[8];
    const float* attn_w  = (const float*)d_in[9];
    const float* attn_b  = (const float*)d_in[10];
    const float* attn_v  = (const float*)d_in[11];
    const float* ln_g    = (const float*)d_in[12];
    const float* ln_b    = (const float*)d_in[13];
    const float* mha_wq  = (const float*)d_in[14];
    const float* mha_wk  = (const float*)d_in[15];
    const float* mha_bq  = (const float*)d_in[17];
    const float* mha_bk  = (const float*)d_in[18];
    const float* fcta_w  = (const float*)d_in[22];
    const float* fcta_b  = (const float*)d_in[23];
    const float* gcn1_w  = (const float*)d_in[24];
    const float* gcn1_b  = (const float*)d_in[25];
    const float* gcn2_w  = (const float*)d_in[26];
    const float* gcn2_b  = (const float*)d_in[27];
    const float* fc_w1   = (const float*)d_in[28];
    const float* fc_b1   = (const float*)d_in[29];
    const float* fc_w2   = (const float*)d_in[30];
    const float* fc_b2   = (const float*)d_in[31];
    float* out = (float*)d_out;

    const int kc_smem = (32 * HSTR + 32 * GHSTR) * 4;  // 72704 B
    cudaFuncSetAttribute(kC, cudaFuncAttributeMaxDynamicSharedMemorySize, kc_smem);

    // NOTE: launch order chosen so the ncu capture slot (#4) lands on kB.
    kP<<<dim3(NN, 14, 5), dim3(32, 32)>>>(gru_whh);
    kP2<<<dim3(NN, 14, 4), dim3(32, 32)>>>(gru_wih);
    kA<<<NN, BT>>>(x, seq1_w1, seq1_b1, seq1_w2, seq1_b2);
    kB<<<dim3(NN, 12), 512>>>(gru_bih);
    kT<<<77, 256>>>(attn_w, mha_wq, mha_wk);
    kC<<<NN, 512, kc_smem>>>(gru_bhh);
    kD<<<NN * BB, 160>>>(attn_b, attn_v, ln_g, ln_b);
    kE1<<<dim3(BB, 2, 5), 160>>>(mha_bq, mha_bk);
    kE2<<<BB * 5, 128>>>();
    kF<<<1, 256>>>(out);
    kG<<<BB, 256>>>(fcta_w, fcta_b, gcn1_w, gcn1_b, gcn2_w, gcn2_b,
                    fc_w1, fc_b1, fc_w2, fc_b2, out);
}

// round 11
// speedup vs baseline: 1.0430x; 1.0430x over previous
#include <cuda_runtime.h>
#include <math.h>

#define NN 140
#define TT 12
#define BB 32
#define HH 128
#define HID 140
#define G3 420   // 3*HID
#define BT 384   // BB*TT

typedef unsigned long long u64;

__device__ __forceinline__ u64 pack2(float s) {
    u64 d;
    asm("mov.b64 %0, {%1, %1};" : "=l"(d) : "f"(s));
    return d;
}
__device__ __forceinline__ void fma2(u64& d, u64 a, u64 b) {
    asm("fma.rn.f32x2 %0, %1, %2, %0;" : "+l"(d) : "l"(a), "l"(b));
}
__device__ __forceinline__ u64 add2(u64 a, u64 b) {
    u64 d;
    asm("add.rn.f32x2 %0, %1, %2;" : "=l"(d) : "l"(a), "l"(b));
    return d;
}

// ---------------- scratch (device globals; no runtime alloc) ----------------
__device__ float g_xsupT[(size_t)NN * HH * BT];       // [n][h][bt]
__device__ float g_gi[(size_t)NN * BT * G3];          // [n][bt][g]
__device__ float g_outs[(size_t)NN * BB * TT * HID];  // [n][b][t][j]
__device__ float g_ln[(size_t)BB * NN * HID];         // [b][n][j]
__device__ float g_q[(size_t)BB * NN * HID];
__device__ float g_k[(size_t)BB * NN * HID];
__device__ float g_att[NN * NN];
__device__ float g_anorm[NN * NN];
__device__ float g_whhT[(size_t)NN * HID * G3];       // [n][jj][g]
__device__ float g_wihT[(size_t)NN * HH * G3];        // [n][k][g]
// packed transposed weights: w4[k4*140 + jp] = {w[jp][4k4..4k4+3]}
__device__ float4 g_wr4[35 * HID];   // attn_w right half (gru_outs part)
__device__ float4 g_wl4[35 * HID];   // attn_w left half (hid part)
__device__ float4 g_wq4[35 * HID];
__device__ float4 g_wk4[35 * HID];

// ---------------- Kernel P: transpose whh -> whhT (tiled) --------------------
__global__ void kP(const float* __restrict__ whh) {
    __shared__ float tile[32][33];
    int n = blockIdx.x, gt = blockIdx.y * 32, jt = blockIdx.z * 32;
    int tx = threadIdx.x, ty = threadIdx.y;
    const float* src = whh + (size_t)n * G3 * HID;
    float* dst = g_whhT + (size_t)n * HID * G3;
    int g = gt + ty, jj = jt + tx;
    tile[ty][tx] = (g < G3 && jj < HID) ? src[(size_t)g * HID + jj] : 0.f;
    __syncthreads();
    int jj2 = jt + ty, g2 = gt + tx;
    if (jj2 < HID && g2 < G3) dst[(size_t)jj2 * G3 + g2] = tile[tx][ty];
}

// ---------------- Kernel P2: transpose wih -> wihT (tiled) -------------------
__global__ void kP2(const float* __restrict__ wih) {
    __shared__ float tile[32][33];
    int n = blockIdx.x, gt = blockIdx.y * 32, jt = blockIdx.z * 32;
    int tx = threadIdx.x, ty = threadIdx.y;
    const float* src = wih + (size_t)n * G3 * HH;
    float* dst = g_wihT + (size_t)n * HH * G3;
    int g = gt + ty, jj = jt + tx;
    tile[ty][tx] = (g < G3 && jj < HH) ? src[(size_t)g * HH + jj] : 0.f;
    __syncthreads();
    int jj2 = jt + ty, g2 = gt + tx;
    if (jj2 < HH && g2 < G3) dst[(size_t)jj2 * G3 + g2] = tile[tx][ty];
}

// ---------------- Kernel T: pack weights k4-major + zero g_att ---------------
__global__ void kT(const float* __restrict__ attn_w, const float* __restrict__ wq,
                   const float* __restrict__ wk) {
    int idx = blockIdx.x * 256 + threadIdx.x;  // 0..19599 (= 4*4900)
    if (idx >= 4 * 4900) return;
    g_att[idx] = 0.f;
    int mat = idx / 4900, r = idx - mat * 4900;
    int k4 = r / HID, jp = r - k4 * HID;
    const float* src;
    if (mat == 0)      src = attn_w + jp * 280 + HID + 4 * k4;
    else if (mat == 1) src = attn_w + jp * 280 + 4 * k4;
    else if (mat == 2) src = wq + jp * HID + 4 * k4;
    else               src = wk + jp * HID + 4 * k4;
    float4 v = make_float4(src[0], src[1], src[2], src[3]);
    float4* dst = (mat == 0) ? g_wr4 : (mat == 1) ? g_wl4 : (mat == 2) ? g_wq4 : g_wk4;
    dst[k4 * HID + jp] = v;
}

// ---------------- Kernel A: fused seq1 MLP -> x_sup^T (K-major) --------------
__global__ void kA(const float* __restrict__ x, const float* __restrict__ w1,
                   const float* __restrict__ b1, const float* __restrict__ w2,
                   const float* __restrict__ b2) {
    int n = blockIdx.x;
    int bt = threadIdx.x;  // 384 threads
    __shared__ float w1s[64], b1s[64], b2s[128];
    __shared__ float w2s[128 * 64];
    for (int i = threadIdx.x; i < 64; i += 384) { w1s[i] = w1[i]; b1s[i] = b1[i]; }
    for (int i = threadIdx.x; i < 128; i += 384) b2s[i] = b2[i];
    for (int i = threadIdx.x; i < 128 * 64; i += 384) w2s[i] = w2[i];
    __syncthreads();
    float s = x[bt * NN + n];
    float h1[64];
#pragma unroll
    for (int e = 0; e < 64; e++) h1[e] = fmaxf(fmaf(s, w1s[e], b1s[e]), 0.f);
    float* dst = g_xsupT + (size_t)n * HH * BT + bt;
    for (int h = 0; h < 128; h++) {
        float acc = b2s[h];
        const float4* wr = (const float4*)&w2s[h * 64];
#pragma unroll
        for (int e4 = 0; e4 < 16; e4++) {
            float4 w = wr[e4];
            acc += w.x * h1[e4 * 4] + w.y * h1[e4 * 4 + 1] + w.z * h1[e4 * 4 + 2] + w.w * h1[e4 * 4 + 3];
        }
        dst[(size_t)h * BT] = fmaxf(acc, 0.f);
    }
}

// ---------------- Kernel B v4: gi = x_sup @ wihT + bih (1024 thr, f32x2) -----
#define XSTR 132
__global__ void __launch_bounds__(1024, 1) kB(const float* __restrict__ bih) {
    __shared__ float xs_s[32 * XSTR];
    int n = blockIdx.x, bt0 = blockIdx.y * 32;
    int tid = threadIdx.x;  // 1024
    for (int idx = tid; idx < 32 * HH; idx += 1024) {
        int k = idx >> 5, bt = idx & 31;
        xs_s[bt * XSTR + k] = g_xsupT[((size_t)n * HH + k) * BT + bt0 + bt];
    }
    __syncthreads();
    int g4 = tid & 127, bgrp = tid >> 7;  // bgrp 0..7, 4 bt each
    if (g4 >= 105) return;
    const float* wT = g_wihT + (size_t)n * HH * G3;
    u64 a01[4], a23[4];
#pragma unroll
    for (int i = 0; i < 4; i++) { a01[i] = 0ull; a23[i] = 0ull; }
#pragma unroll 4
    for (int k4 = 0; k4 < 32; k4++) {
        ulonglong2 w0 = __ldg((const ulonglong2*)&wT[(size_t)(4 * k4 + 0) * G3 + 4 * g4]);
        ulonglong2 w1 = __ldg((const ulonglong2*)&wT[(size_t)(4 * k4 + 1) * G3 + 4 * g4]);
        ulonglong2 w2 = __ldg((const ulonglong2*)&wT[(size_t)(4 * k4 + 2) * G3 + 4 * g4]);
        ulonglong2 w3 = __ldg((const ulonglong2*)&wT[(size_t)(4 * k4 + 3) * G3 + 4 * g4]);
#pragma unroll
        for (int i = 0; i < 4; i++) {
            float4 xv = *(const float4*)&xs_s[(bgrp * 4 + i) * XSTR + 4 * k4];
            u64 px = pack2(xv.x), py = pack2(xv.y), pz = pack2(xv.z), pw = pack2(xv.w);
            fma2(a01[i], px, w0.x); fma2(a23[i], px, w0.y);
            fma2(a01[i], py, w1.x); fma2(a23[i], py, w1.y);
            fma2(a01[i], pz, w2.x); fma2(a23[i], pz, w2.y);
            fma2(a01[i], pw, w3.x); fma2(a23[i], pw, w3.y);
        }
    }
    ulonglong2 bb = *(const ulonglong2*)&bih[n * G3 + 4 * g4];
#pragma unroll
    for (int i = 0; i < 4; i++) {
        int bt = bt0 + bgrp * 4 + i;
        ulonglong2 o;
        o.x = add2(a01[i], bb.x);
        o.y = add2(a23[i], bb.y);
        *(ulonglong2*)&g_gi[((size_t)n * BT + bt) * G3 + 4 * g4] = o;
    }
}

// ---------------- Kernel C v5: GRU scan (1024 thr, f32x2) --------------------
#define HSTR 144
#define GHSTR 424
__global__ void __launch_bounds__(1024, 1) kC(const float* __restrict__ bhh) {
    extern __shared__ float sm[];
    float* h_s = sm;                 // 32*144
    float* gh_s = sm + 32 * HSTR;    // 32*424
    int n = blockIdx.x, tid = threadIdx.x;  // 1024 thr
    for (int i = tid; i < 32 * HSTR; i += 1024) h_s[i] = 0.f;
    int bgrp = tid >> 7;          // 0..7  (4 batches each)
    int g4 = tid & 127;           // float4 group of g; active if < 105
    bool act = g4 < 105;
    const float* whhT_n = g_whhT + (size_t)n * HID * G3;
    const float* bhh_n = bhh + n * G3;
    const float* gi_n = g_gi + (size_t)n * BT * G3;
    float* outs_n = g_outs + (size_t)n * BB * TT * HID;
    u64 b01 = 0ull, b23 = 0ull;
    if (act) {
        ulonglong2 bb = *(const ulonglong2*)&bhh_n[4 * g4];
        b01 = bb.x; b23 = bb.y;
    }
    for (int t = 0; t < TT; t++) {
        __syncthreads();
        if (act) {
            u64 a01[4], a23[4];
#pragma unroll
            for (int i = 0; i < 4; i++) { a01[i] = 0ull; a23[i] = 0ull; }
#pragma unroll 5
            for (int jj4 = 0; jj4 < 35; jj4++) {
                ulonglong2 w0 = __ldg((const ulonglong2*)&whhT_n[(size_t)(jj4 * 4 + 0) * G3 + 4 * g4]);
                ulonglong2 w1 = __ldg((const ulonglong2*)&whhT_n[(size_t)(jj4 * 4 + 1) * G3 + 4 * g4]);
                ulonglong2 w2 = __ldg((const ulonglong2*)&whhT_n[(size_t)(jj4 * 4 + 2) * G3 + 4 * g4]);
                ulonglong2 w3 = __ldg((const ulonglong2*)&whhT_n[(size_t)(jj4 * 4 + 3) * G3 + 4 * g4]);
#pragma unroll
                for (int i = 0; i < 4; i++) {
                    float4 hv = *(const float4*)&h_s[(bgrp * 4 + i) * HSTR + jj4 * 4];
                    u64 px = pack2(hv.x), py = pack2(hv.y), pz = pack2(hv.z), pw = pack2(hv.w);
                    fma2(a01[i], px, w0.x); fma2(a23[i], px, w0.y);
                    fma2(a01[i], py, w1.x); fma2(a23[i], py, w1.y);
                    fma2(a01[i], pz, w2.x); fma2(a23[i], pz, w2.y);
                    fma2(a01[i], pw, w3.x); fma2(a23[i], pw, w3.y);
                }
            }
#pragma unroll
            for (int i = 0; i < 4; i++) {
                ulonglong2 o;
                o.x = add2(a01[i], b01);
                o.y = add2(a23[i], b23);
                *(ulonglong2*)&gh_s[(bgrp * 4 + i) * GHSTR + 4 * g4] = o;
            }
        }
        __syncthreads();
        for (int idx = tid; idx < BB * HID; idx += 1024) {
            int b = idx / HID, j = idx - b * HID;
            const float* gi = gi_n + (size_t)(b * TT + t) * G3;
            float gir = gi[j], giz = gi[HID + j], gin = gi[2 * HID + j];
            float ghr = gh_s[b * GHSTR + j];
            float ghz = gh_s[b * GHSTR + HID + j];
            float ghn = gh_s[b * GHSTR + 2 * HID + j];
            float r = 1.f / (1.f + expf(-(gir + ghr)));
            float z = 1.f / (1.f + expf(-(giz + ghz)));
            float nv = tanhf(gin + r * ghn);
            float hold = h_s[b * HSTR + j];
            float hnew = (1.f - z) * nv + z * hold;
            h_s[b * HSTR + j] = hnew;
            outs_n[(size_t)(b * TT + t) * HID + j] = hnew;
        }
    }
}

// ---------------- Kernel D: temporal attention + LayerNorm (jp-per-thread) ---
__global__ void kD(const float* __restrict__ attn_b, const float* __restrict__ attn_v,
                   const float* __restrict__ ln_g, const float* __restrict__ ln_b) {
    __shared__ float outs_s[TT * HID];   // 1680
    __shared__ float wpart[5][12];
    __shared__ float ws[12];
    __shared__ float red[5][2];
    __shared__ float stats[2];
    int bid = blockIdx.x;
    int n = bid >> 5, b = bid & 31;
    int tid = threadIdx.x;  // 160
    const float* src = g_outs + (size_t)(n * BB + b) * TT * HID;
    for (int i = tid; i < TT * HID; i += 160) outs_s[i] = src[i];
    __syncthreads();
    int jp = tid;
    bool act = jp < HID;
    float acc[13];
#pragma unroll
    for (int t = 0; t < 13; t++) acc[t] = 0.f;
    if (act) {
#pragma unroll 5
        for (int k4 = 0; k4 < 35; k4++) {
            float4 wr = g_wr4[k4 * HID + jp];
            float4 wl = g_wl4[k4 * HID + jp];
#pragma unroll
            for (int t = 0; t < 12; t++) {
                float4 s = *(const float4*)&outs_s[t * HID + 4 * k4];
                acc[t] += s.x * wr.x + s.y * wr.y + s.z * wr.z + s.w * wr.w;
                if (t == 11) acc[12] += s.x * wl.x + s.y * wl.y + s.z * wl.z + s.w * wl.w;
            }
        }
    }
    float eh = act ? (acc[12] + attn_b[jp]) : 0.f;
    float vv = act ? attn_v[jp] : 0.f;
    float p[12];
#pragma unroll
    for (int t = 0; t < 12; t++) p[t] = vv * tanhf(eh + acc[t]);
#pragma unroll
    for (int o = 16; o; o >>= 1)
#pragma unroll
        for (int t = 0; t < 12; t++) p[t] += __shfl_xor_sync(0xffffffff, p[t], o);
    int wid = tid >> 5, lane = tid & 31;
    if (lane == 0)
#pragma unroll
        for (int t = 0; t < 12; t++) wpart[wid][t] = p[t];
    __syncthreads();
    if (tid == 0) {
        float scv[12], m = -3.4e38f;
#pragma unroll
        for (int t = 0; t < 12; t++) {
            float v = wpart[0][t] + wpart[1][t] + wpart[2][t] + wpart[3][t] + wpart[4][t];
            scv[t] = v;
            m = fmaxf(m, v);
        }
        float ssum = 0.f;
#pragma unroll
        for (int t = 0; t < 12; t++) { float e = expf(scv[t] - m); ws[t] = e; ssum += e; }
        float inv = 1.f / ssum;
#pragma unroll
        for (int t = 0; t < 12; t++) ws[t] *= inv;
    }
    __syncthreads();
    float pre = 0.f;
    if (act) {
        pre = outs_s[11 * HID + jp];  // + hid
#pragma unroll
        for (int t = 0; t < 12; t++) pre += ws[t] * outs_s[t * HID + jp];
    }
    float s = act ? pre : 0.f, q = act ? pre * pre : 0.f;
#pragma unroll
    for (int o = 16; o; o >>= 1) {
        s += __shfl_xor_sync(0xffffffff, s, o);
        q += __shfl_xor_sync(0xffffffff, q, o);
    }
    if (lane == 0) { red[wid][0] = s; red[wid][1] = q; }
    __syncthreads();
    if (tid == 0) {
        float ss = red[0][0] + red[1][0] + red[2][0] + red[3][0] + red[4][0];
        float qq = red[0][1] + red[1][1] + red[2][1] + red[3][1] + red[4][1];
        float mu = ss * (1.f / HID);
        stats[0] = mu;
        stats[1] = qq * (1.f / HID) - mu * mu;
    }
    __syncthreads();
    if (act) {
        float mu = stats[0], inv = rsqrtf(stats[1] + 1e-5f);
        g_ln[((size_t)b * NN + n) * HID + jp] = (pre - mu) * inv * ln_g[jp] + ln_b[jp];
    }
}

// ---------------- Kernel E1: q,k projections (jp-per-thread, packed W) -------
__global__ void kE1(const float* __restrict__ bq, const float* __restrict__ bk) {
    __shared__ float src_s[28 * HID];
    int b = blockIdx.x, mat = blockIdx.y, chunk = blockIdx.z;
    int tid = threadIdx.x;  // 160
    int i0 = chunk * 28;
    const float* src = g_ln + (size_t)b * NN * HID + (size_t)i0 * HID;
    for (int i = tid; i < 28 * HID; i += 160) src_s[i] = src[i];
    __syncthreads();
    int jp = tid;
    if (jp >= HID) return;
    const float4* wmat = mat ? g_wk4 : g_wq4;
    float acc[28];
#pragma unroll
    for (int ii = 0; ii < 28; ii++) acc[ii] = 0.f;
#pragma unroll 5
    for (int k4 = 0; k4 < 35; k4++) {
        float4 w = wmat[k4 * HID + jp];
#pragma unroll
        for (int ii = 0; ii < 28; ii++) {
            float4 sv = *(const float4*)&src_s[ii * HID + 4 * k4];
            acc[ii] += sv.x * w.x + sv.y * w.y + sv.z * w.z + sv.w * w.w;
        }
    }
    float bias = (mat ? bk : bq)[jp];
    float* dst = (mat ? g_k : g_q) + (size_t)b * NN * HID;
#pragma unroll
    for (int ii = 0; ii < 28; ii++) dst[(size_t)(i0 + ii) * HID + jp] = acc[ii] + bias;
}

// ---------------- Kernel E2: per (b,head) softmax, accumulate mean -----------
__global__ void kE2() {
    __shared__ float qs[NN * 28], ks[NN * 28];
    int bid = blockIdx.x;
    int b = bid / 5, h = bid - b * 5;
    int tid = threadIdx.x;  // 128
    const float* qsrc = g_q + (size_t)b * NN * HID + h * 28;
    const float* ksrc = g_k + (size_t)b * NN * HID + h * 28;
    for (int idx = tid; idx < NN * 28; idx += 128) {
        int i = idx / 28, d = idx - i * 28;
        qs[idx] = qsrc[i * HID + d];
        ks[idx] = ksrc[i * HID + d];
    }
    __syncthreads();
    const float scale = 0.1889822365046136f;  // 1/sqrt(28)
    int wid = tid >> 5, lane = tid & 31;
    for (int i = wid; i < NN; i += 4) {
        float lg[5];
#pragma unroll
        for (int u = 0; u < 5; u++) {
            int k = lane + 32 * u;
            float acc = -3.4e38f;
            if (k < NN) {
                acc = 0.f;
                const float4* a4 = (const float4*)&qs[i * 28];
                const float4* b4 = (const float4*)&ks[k * 28];
#pragma unroll
                for (int q = 0; q < 7; q++) {
                    float4 a = a4[q], c = b4[q];
                    acc += a.x * c.x + a.y * c.y + a.z * c.z + a.w * c.w;
                }
                acc *= scale;
            }
            lg[u] = acc;
        }
        float m = lg[0];
#pragma unroll
        for (int u = 1; u < 5; u++) m = fmaxf(m, lg[u]);
        for (int o = 16; o; o >>= 1) m = fmaxf(m, __shfl_xor_sync(0xffffffff, m, o));
        float s = 0.f, e[5];
#pragma unroll
        for (int u = 0; u < 5; u++) {
            int k = lane + 32 * u;
            e[u] = (k < NN) ? expf(lg[u] - m) : 0.f;
            s += e[u];
        }
        for (int o = 16; o; o >>= 1) s += __shfl_xor_sync(0xffffffff, s, o);
        float inv = 1.f / (160.f * s);
#pragma unroll
        for (int u = 0; u < 5; u++) {
            int k = lane + 32 * u;
            if (k < NN) atomicAdd(&g_att[i * NN + k], e[u] * inv);
        }
    }
}

// ---------------- Kernel F: A_norm + write attention output ------------------
__global__ void kF(float* __restrict__ d_out) {
    __shared__ float dinv[NN];
    int tid = threadIdx.x;  // 256
    for (int i = tid; i < NN; i += 256) {
        float s = 1.f;
        for (int j = 0; j < NN; j++) s += g_att[i * NN + j];
        dinv[i] = 1.f / sqrtf(s);
    }
    __syncthreads();
    for (int idx = tid; idx < NN * NN; idx += 256) {
        int i = idx / NN, j = idx - i * NN;
        float a = g_att[idx] + (i == j ? 1.f : 0.f);
        g_anorm[idx] = dinv[i] * a * dinv[j];
        d_out[BB * 3 * NN + idx] = g_att[idx];
    }
}

// ---------------- Kernel G: fcta + GCN x2 + FC head + output -----------------
__global__ void kG(const float* __restrict__ fcta_w, const float* __restrict__ fcta_b,
                   const float* __restrict__ gcn1_w, const float* __restrict__ gcn1_b,
                   const float* __restrict__ gcn2_w, const float* __restrict__ gcn2_b,
                   const float* __restrict__ fc_w1, const float* __restrict__ fc_b1,
                   const float* __restrict__ fc_w2, const float* __restrict__ fc_b2,
                   float* __restrict__ d_out) {
    __shared__ float wrs[NN * TT];   // reused as f1
    __shared__ float Y[NN * 32];
    __shared__ float X[NN * 32];
    int b = blockIdx.x;
    int tid = threadIdx.x;  // 256
    const float* ln = g_ln + (size_t)b * NN * HID;
    for (int idx = tid; idx < NN * TT; idx += 256) {
        int i = idx / TT, t = idx - i * TT;
        const float4* s4 = (const float4*)(ln + i * HID);
        const float4* w4 = (const float4*)(fcta_w + t * HID);
        float acc = fcta_b[t];
#pragma unroll 7
        for (int q = 0; q < 35; q++) {
            float4 a = s4[q], c = w4[q];
            acc += a.x * c.x + a.y * c.y + a.z * c.z + a.w * c.w;
        }
        wrs[idx] = acc;
    }
    __syncthreads();
    for (int idx = tid; idx < NN * 32; idx += 256) {
        int i = idx >> 5, c = idx & 31;
        float acc = 0.f;
#pragma unroll
        for (int t = 0; t < TT; t++) acc += wrs[i * TT + t] * gcn1_w[t * 32 + c];
        Y[idx] = acc;
    }
    __syncthreads();
    for (int idx = tid; idx < NN * 32; idx += 256) {
        int i = idx >> 5, c = idx & 31;
        float acc = gcn1_b[c];
        const float* ar = g_anorm + i * NN;
        for (int j = 0; j < NN; j++) acc += __ldg(&ar[j]) * Y[j * 32 + c];
        X[idx] = fmaxf(acc, 0.f);
    }
    __syncthreads();
    for (int idx = tid; idx < NN * 32; idx += 256) {
        int i = idx >> 5, c = idx & 31;
        float acc = 0.f;
#pragma unroll
        for (int cc = 0; cc < 32; cc++) acc += X[i * 32 + cc] * gcn2_w[cc * 32 + c];
        Y[idx] = acc;
    }
    __syncthreads();
    for (int idx = tid; idx < NN * 32; idx += 256) {
        int i = idx >> 5, c = idx & 31;
        float acc = gcn2_b[c];
        const float* ar = g_anorm + i * NN;
        for (int j = 0; j < NN; j++) acc += __ldg(&ar[j]) * Y[j * 32 + c];
        X[idx] = fmaxf(acc, 0.f);
    }
    __syncthreads();
    for (int idx = tid; idx < NN * TT; idx += 256) {
        int i = idx / TT, t = idx - i * TT;
        float acc = fc_b1[t];
#pragma unroll
        for (int c = 0; c < 32; c++) acc += X[i * 32 + c] * fc_w1[t * 32 + c];
        wrs[idx] = (acc > 0.f) ? acc : 0.01f * acc;
    }
    __syncthreads();
    for (int idx = tid; idx < NN * 3; idx += 256) {
        int hz = idx / NN, i = idx - hz * NN;
        float acc = fc_b2[hz];
#pragma unroll
        for (int t = 0; t < TT; t++) acc += wrs[i * TT + t] * fc_w2[hz * TT + t];
        d_out[(b * 3 + hz) * NN + i] = acc;
    }
}

// ---------------- launch ------------------------------------------------------
extern "C" void kernel_launch(void* const* d_in, const int* in_sizes, int n_in,
                              void* d_out, int out_size) {
    const float* x       = (const float*)d_in[0];
    const float* seq1_w1 = (const float*)d_in[1];
    const float* seq1_b1 = (const float*)d_in[2];
    const float* seq1_w2 = (const float*)d_in[3];
    const float* seq1_b2 = (const float*)d_in[4];
    const float* gru_wih = (const float*)d_in[5];
    const float* gru_whh = (const float*)d_in[6];
    const float* gru_bih = (const float*)d_in[7];
    const float* gru_bhh = (const float*)d_in[8];
    const float* attn_w  = (const float*)d_in[9];
    const float* attn_b  = (const float*)d_in[10];
    const float* attn_v  = (const float*)d_in[11];
    const float* ln_g    = (const float*)d_in[12];
    const float* ln_b    = (const float*)d_in[13];
    const float* mha_wq  = (const float*)d_in[14];
    const float* mha_wk  = (const float*)d_in[15];
    const float* mha_bq  = (const float*)d_in[17];
    const float* mha_bk  = (const float*)d_in[18];
    const float* fcta_w  = (const float*)d_in[22];
    const float* fcta_b  = (const float*)d_in[23];
    const float* gcn1_w  = (const float*)d_in[24];
    const float* gcn1_b  = (const float*)d_in[25];
    const float* gcn2_w  = (const float*)d_in[26];
    const float* gcn2_b  = (const float*)d_in[27];
    const float* fc_w1   = (const float*)d_in[28];
    const float* fc_b1   = (const float*)d_in[29];
    const float* fc_w2   = (const float*)d_in[30];
    const float* fc_b2   = (const float*)d_in[31];
    float* out = (float*)d_out;

    const int kc_smem = (32 * HSTR + 32 * GHSTR) * 4;  // 72704 B
    cudaFuncSetAttribute(kC, cudaFuncAttributeMaxDynamicSharedMemorySize, kc_smem);

    // NOTE: launch order chosen so the ncu capture slot (#4) lands on kB.
    kP<<<dim3(NN, 14, 5), dim3(32, 32)>>>(gru_whh);
    kP2<<<dim3(NN, 14, 4), dim3(32, 32)>>>(gru_wih);
    kA<<<NN, BT>>>(x, seq1_w1, seq1_b1, seq1_w2, seq1_b2);
    kB<<<dim3(NN, 12), 1024>>>(gru_bih);
    kT<<<77, 256>>>(attn_w, mha_wq, mha_wk);
    kC<<<NN, 1024, kc_smem>>>(gru_bhh);
    kD<<<NN * BB, 160>>>(attn_b, attn_v, ln_g, ln_b);
    kE1<<<dim3(BB, 2, 5), 160>>>(mha_bq, mha_bk);
    kE2<<<BB * 5, 128>>>();
    kF<<<1, 256>>>(out);
    kG<<<BB, 256>>>(fcta_w, fcta_b, gcn1_w, gcn1_b, gcn2_w, gcn2_b,
                    fc_w1, fc_b1, fc_w2, fc_b2, out);
}